// round 7
// baseline (speedup 1.0000x reference)
#include <cuda_runtime.h>
#include <cstdint>

#define NNODES 50000
#define EEDGES 800000
#define DIN 512
#define DHID 512
#define DOUT 256

// ---------------- static device scratch (no allocations allowed) ----------------
__device__ float    g_P1[(size_t)NNODES * DIN];    // propagate(x)
__device__ float    g_T [(size_t)NNODES * DOUT];   // emb @ W2^T
__device__ float    g_emb[(size_t)NNODES * DHID];  // embedding scratch (if out buffer lacks space)
__device__ int      g_deg[NNODES];
__device__ int      g_cursor[NNODES];
__device__ int      g_rowptr[NNODES + 1];
__device__ int      g_colidx[EEDGES];
__device__ float    g_dinv[NNODES];
__device__ unsigned g_wl[(size_t)NNODES * DHID];   // worklist of nonzero h positions
__device__ int      g_wlcount;
__device__ int      g_is64;

// ---------------- packed f32x2 helpers ----------------
__device__ __forceinline__ unsigned long long pk2(float a, float b) {
    unsigned long long r;
    asm("mov.b64 %0, {%1, %2};" : "=l"(r) : "f"(a), "f"(b));
    return r;
}
__device__ __forceinline__ void fma2(unsigned long long& c, unsigned long long a, unsigned long long b) {
    asm("fma.rn.f32x2 %0, %1, %2, %0;" : "+l"(c) : "l"(a), "l"(b));
}
__device__ __forceinline__ float2 up2(unsigned long long v) {
    float2 f;
    asm("mov.b64 {%0, %1}, %2;" : "=f"(f.x), "=f"(f.y) : "l"(v));
    return f;
}

// ---------------- edge_index dtype probe + safe accessor ----------------
__global__ void k_detect(const unsigned* __restrict__ ei32, int E) {
    int any = 0;
    for (int i = threadIdx.x; i < 1024; i += blockDim.x)
        if (ei32[2 * i + 1] != 0u) any = 1;
    int found = __syncthreads_or(any);
    if (threadIdx.x == 0) g_is64 = found ? 0 : 1;
}

__device__ __forceinline__ int load_idx(const void* ei, int E, int which, int i, int n) {
    long long v;
    if (g_is64) v = ((const long long*)ei)[(size_t)which * E + i];
    else        v = (long long)((const int*)ei)[(size_t)which * E + i];
    if (v < 0) v = 0;
    if (v > n - 1) v = n - 1;
    return (int)v;
}

// ---------------- graph setup kernels ----------------
__global__ void k_init(int n) {
    int i = blockIdx.x * blockDim.x + threadIdx.x;
    if (i < n) { g_deg[i] = 0; g_cursor[i] = 0; }
    if (i == 0) g_wlcount = 0;
}

__global__ void k_count(const void* __restrict__ ei, int E, int n) {
    int i = blockIdx.x * blockDim.x + threadIdx.x;
    if (i < E) {
        int d = load_idx(ei, E, 1, i, n);
        atomicAdd(&g_deg[d], 1);
    }
}

__global__ void k_dinv(int n) {
    int i = blockIdx.x * blockDim.x + threadIdx.x;
    if (i < n) g_dinv[i] = rsqrtf((float)(g_deg[i] + 1));
}

// exclusive scan of g_deg -> g_rowptr, single block of 1024 with shuffle scans
__global__ void k_scan(int n) {
    __shared__ int warpsum[32];
    __shared__ int s_carry;
    int tid = threadIdx.x, lane = tid & 31, wid = tid >> 5;
    if (tid == 0) s_carry = 0;
    __syncthreads();
    for (int base = 0; base < n; base += 1024) {
        int i = base + tid;
        int v = (i < n) ? g_deg[i] : 0;
        int incl = v;
        #pragma unroll
        for (int off = 1; off < 32; off <<= 1) {
            int t = __shfl_up_sync(0xffffffffu, incl, off);
            if (lane >= off) incl += t;
        }
        if (lane == 31) warpsum[wid] = incl;
        __syncthreads();
        if (wid == 0) {
            int w = warpsum[lane];
            int ws = w;
            #pragma unroll
            for (int off = 1; off < 32; off <<= 1) {
                int t = __shfl_up_sync(0xffffffffu, ws, off);
                if (lane >= off) ws += t;
            }
            warpsum[lane] = ws - w;  // exclusive warp offsets
        }
        __syncthreads();
        int excl = s_carry + warpsum[wid] + incl - v;
        if (i < n) g_rowptr[i] = excl;
        __syncthreads();
        if (tid == 1023) s_carry += warpsum[31] + incl;
        __syncthreads();
    }
    if (threadIdx.x == 0) g_rowptr[n] = s_carry;
}

__global__ void k_fill(const void* __restrict__ ei, int E, int n) {
    int i = blockIdx.x * blockDim.x + threadIdx.x;
    if (i < E) {
        int s = load_idx(ei, E, 0, i, n);
        int d = load_idx(ei, E, 1, i, n);
        int pos = atomicAdd(&g_cursor[d], 1);
        int slot = g_rowptr[d] + pos;
        if (slot < E) g_colidx[slot] = s;
    }
}

// ---------------- threefry2x32, exact JAX replication, key = (0, 42) ----------------
__device__ __forceinline__ void threefry2x32(unsigned x0, unsigned x1, unsigned& o0, unsigned& o1) {
    const unsigned k0 = 0u, k1 = 42u, k2 = 0x1BD11BDAu ^ k0 ^ k1;
    x0 += k0; x1 += k1;
#define TFR(r) { x0 += x1; x1 = (x1 << (r)) | (x1 >> (32 - (r))); x1 ^= x0; }
    TFR(13) TFR(15) TFR(26) TFR(6)   x0 += k1; x1 += k2 + 1u;
    TFR(17) TFR(29) TFR(16) TFR(24)  x0 += k2; x1 += k0 + 2u;
    TFR(13) TFR(15) TFR(26) TFR(6)   x0 += k0; x1 += k1 + 3u;
    TFR(17) TFR(29) TFR(16) TFR(24)  x0 += k1; x1 += k2 + 4u;
    TFR(13) TFR(15) TFR(26) TFR(6)   x0 += k2; x1 += k0 + 5u;
#undef TFR
    o0 = x0; o1 = x1;
}

// ---------------- dropout via PARTITIONABLE threefry (jax_threefry_partitionable=True) ----
// For flat element f: counter = (hi, lo) = (0, f); bits = o0 ^ o1; keep <=> bit31 == 0.
// We only hash positions where h != 0 (ReLU zeros are dropout-invariant), so first
// compact the nonzero positions of h into g_wl, then hash+apply in place.

__global__ void k_compact(const float* __restrict__ h, int total) {
    int tid = threadIdx.x;
    int gid = blockIdx.x * blockDim.x + tid;
    int lane = tid & 31, wid = tid >> 5;
    float v = (gid < total) ? h[gid] : 0.f;
    unsigned ball = __ballot_sync(0xffffffffu, v != 0.f);
    __shared__ int s_woff[8];
    __shared__ int s_base;
    if (lane == 0) s_woff[wid] = __popc(ball);
    __syncthreads();
    if (tid == 0) {
        int s = 0;
        #pragma unroll
        for (int w = 0; w < 8; w++) { int c = s_woff[w]; s_woff[w] = s; s += c; }
        s_base = atomicAdd(&g_wlcount, s);
    }
    __syncthreads();
    if (v != 0.f) {
        int rank = __popc(ball & ((1u << lane) - 1u));
        g_wl[s_base + s_woff[wid] + rank] = (unsigned)gid;
    }
}

__global__ void k_maskapply(float* __restrict__ emb) {
    int total = g_wlcount;
    int stride = gridDim.x * blockDim.x;
    for (int i = blockIdx.x * blockDim.x + threadIdx.x; i < total; i += stride) {
        unsigned f = g_wl[i];
        unsigned o0, o1;
        threefry2x32(0u, f, o0, o1);
        float h = emb[f];
        emb[f] = ((o0 ^ o1) & 0x80000000u) ? 0.f : 2.f * h;
    }
}

// ---------------- propagate: warp-per-node, CSR gather, no feature atomics ----------------
template <int D, int SRC_EXT>
__global__ void k_prop(const float* __restrict__ Xext, float* __restrict__ Yext,
                       const float* __restrict__ bias, int n) {
    int gw = (blockIdx.x * blockDim.x + threadIdx.x) >> 5;
    int lane = threadIdx.x & 31;
    if (gw >= n) return;
    const float* X = SRC_EXT ? Xext : g_T;
    float*       Y = SRC_EXT ? g_P1 : Yext;
    const int G = D / 128;

    float di = g_dinv[gw];
    const float4* xs = (const float4*)(X + (size_t)gw * D);
    float4 acc[G];
    float ws = di * di;  // self loop
    #pragma unroll
    for (int g = 0; g < G; g++) {
        float4 v = xs[lane + 32 * g];
        acc[g] = make_float4(ws * v.x, ws * v.y, ws * v.z, ws * v.w);
    }
    int e0 = g_rowptr[gw], e1 = g_rowptr[gw + 1];
    int e = e0;
    for (; e + 1 < e1; e += 2) {
        int j0 = g_colidx[e], j1 = g_colidx[e + 1];
        float w0 = di * g_dinv[j0], w1 = di * g_dinv[j1];
        const float4* x0 = (const float4*)(X + (size_t)j0 * D);
        const float4* x1 = (const float4*)(X + (size_t)j1 * D);
        #pragma unroll
        for (int g = 0; g < G; g++) {
            float4 v0 = x0[lane + 32 * g];
            float4 v1 = x1[lane + 32 * g];
            acc[g].x = fmaf(w0, v0.x, fmaf(w1, v1.x, acc[g].x));
            acc[g].y = fmaf(w0, v0.y, fmaf(w1, v1.y, acc[g].y));
            acc[g].z = fmaf(w0, v0.z, fmaf(w1, v1.z, acc[g].z));
            acc[g].w = fmaf(w0, v0.w, fmaf(w1, v1.w, acc[g].w));
        }
    }
    if (e < e1) {
        int j0 = g_colidx[e];
        float w0 = di * g_dinv[j0];
        const float4* x0 = (const float4*)(X + (size_t)j0 * D);
        #pragma unroll
        for (int g = 0; g < G; g++) {
            float4 v0 = x0[lane + 32 * g];
            acc[g].x = fmaf(w0, v0.x, acc[g].x);
            acc[g].y = fmaf(w0, v0.y, acc[g].y);
            acc[g].z = fmaf(w0, v0.z, acc[g].z);
            acc[g].w = fmaf(w0, v0.w, acc[g].w);
        }
    }
    if (bias) {
        const float4* bb = (const float4*)bias;
        #pragma unroll
        for (int g = 0; g < G; g++) {
            float4 b = bb[lane + 32 * g];
            acc[g].x += b.x; acc[g].y += b.y; acc[g].z += b.z; acc[g].w += b.w;
        }
    }
    float4* ys = (float4*)(Y + (size_t)gw * D);
    #pragma unroll
    for (int g = 0; g < G; g++) ys[lane + 32 * g] = acc[g];
}

// ---------------- GEMM: C = A @ W^T, 128x128x16 tiles, packed fma.rn.f32x2 ----------------
// EPI==1: A = g_P1, C = full ? Cext : g_emb, with bias+relu epilogue (K=512, ncol=512)
// EPI==0: A = full ? Aext : g_emb, C = g_T, plain store (K=512, ncol=256)
#define STORE_TILE(buf)                                                        \
    {                                                                          \
        int kb = lkq * 4;                                                      \
        As[buf][(kb + 0) * S + lrow]      = ra0.x;                             \
        As[buf][(kb + 1) * S + lrow]      = ra0.y;                             \
        As[buf][(kb + 2) * S + lrow]      = ra0.z;                             \
        As[buf][(kb + 3) * S + lrow]      = ra0.w;                             \
        As[buf][(kb + 0) * S + lrow + 64] = ra1.x;                             \
        As[buf][(kb + 1) * S + lrow + 64] = ra1.y;                             \
        As[buf][(kb + 2) * S + lrow + 64] = ra1.z;                             \
        As[buf][(kb + 3) * S + lrow + 64] = ra1.w;                             \
        Bs[buf][(kb + 0) * S + lrow]      = rw0.x;                             \
        Bs[buf][(kb + 1) * S + lrow]      = rw0.y;                             \
        Bs[buf][(kb + 2) * S + lrow]      = rw0.z;                             \
        Bs[buf][(kb + 3) * S + lrow]      = rw0.w;                             \
        Bs[buf][(kb + 0) * S + lrow + 64] = rw1.x;                             \
        Bs[buf][(kb + 1) * S + lrow + 64] = rw1.y;                             \
        Bs[buf][(kb + 2) * S + lrow + 64] = rw1.z;                             \
        Bs[buf][(kb + 3) * S + lrow + 64] = rw1.w;                             \
    }

template <int EPI>
__global__ __launch_bounds__(256, 2) void k_gemm(const float* __restrict__ Aext,
                                                 const float* __restrict__ Wm,
                                                 const float* __restrict__ bias,
                                                 float* __restrict__ Cext,
                                                 int full, int n) {
    const int S = 132;  // padded smem row stride (floats); float4-aligned, low store conflicts
    __shared__ float As[2][16 * S];
    __shared__ float Bs[2][16 * S];

    const float* A;
    float* C;
    if (EPI == 1) { A = g_P1; C = full ? Cext : g_emb; }
    else          { A = full ? Aext : g_emb; C = g_T; }

    int tid = threadIdx.x;
    int br = blockIdx.x, bc = blockIdx.y;
    int ncol = gridDim.y << 7;

    int lrow = tid >> 2;
    int lkq  = tid & 3;
    long ar0 = (long)br * 128 + lrow;       if (ar0 > n - 1) ar0 = n - 1;
    long ar1 = (long)br * 128 + lrow + 64;  if (ar1 > n - 1) ar1 = n - 1;
    long wr0 = (long)bc * 128 + lrow;
    long wr1 = wr0 + 64;
    const float* pa0 = A  + ar0 * 512 + lkq * 4;
    const float* pa1 = A  + ar1 * 512 + lkq * 4;
    const float* pw0 = Wm + wr0 * 512 + lkq * 4;
    const float* pw1 = Wm + wr1 * 512 + lkq * 4;

    float4 ra0 = *(const float4*)pa0;
    float4 ra1 = *(const float4*)pa1;
    float4 rw0 = *(const float4*)pw0;
    float4 rw1 = *(const float4*)pw1;
    STORE_TILE(0);
    __syncthreads();

    unsigned long long acc[8][4];
    #pragma unroll
    for (int i = 0; i < 8; i++)
        #pragma unroll
        for (int p = 0; p < 4; p++) acc[i][p] = 0ull;

    int tr = tid >> 4, tc = tid & 15;

    #pragma unroll 1
    for (int kt = 0; kt < 32; ++kt) {
        int cur = kt & 1;
        if (kt < 31) {  // prefetch next k-tile into registers
            ra0 = *(const float4*)(pa0 + (kt + 1) * 16);
            ra1 = *(const float4*)(pa1 + (kt + 1) * 16);
            rw0 = *(const float4*)(pw0 + (kt + 1) * 16);
            rw1 = *(const float4*)(pw1 + (kt + 1) * 16);
        }
        #pragma unroll
        for (int k = 0; k < 16; k++) {
            const float* as = &As[cur][k * S + tr * 8];
            float4 a0 = *(const float4*)as;
            float4 a1 = *(const float4*)(as + 4);
            const float* bs = &Bs[cur][k * S + tc * 8];
            float4 b0  = *(const float4*)bs;
            float4 b1v = *(const float4*)(bs + 4);
            unsigned long long bp0 = pk2(b0.x, b0.y),   bp1 = pk2(b0.z, b0.w);
            unsigned long long bp2 = pk2(b1v.x, b1v.y), bp3 = pk2(b1v.z, b1v.w);
            float av[8] = {a0.x, a0.y, a0.z, a0.w, a1.x, a1.y, a1.z, a1.w};
            #pragma unroll
            for (int i = 0; i < 8; i++) {
                unsigned long long ap = pk2(av[i], av[i]);
                fma2(acc[i][0], ap, bp0);
                fma2(acc[i][1], ap, bp1);
                fma2(acc[i][2], ap, bp2);
                fma2(acc[i][3], ap, bp3);
            }
        }
        if (kt < 31) { int nxt = cur ^ 1; STORE_TILE(nxt); }
        __syncthreads();
    }

    int c0 = bc * 128 + tc * 8;
    if (EPI == 1) {
        float4 bv0 = *(const float4*)(bias + c0);
        float4 bv1 = *(const float4*)(bias + c0 + 4);
        float bb[8] = {bv0.x, bv0.y, bv0.z, bv0.w, bv1.x, bv1.y, bv1.z, bv1.w};
        #pragma unroll
        for (int i = 0; i < 8; i++) {
            int r = br * 128 + tr * 8 + i;
            if (r >= n) break;
            float o[8];
            #pragma unroll
            for (int p = 0; p < 4; p++) {
                float2 v = up2(acc[i][p]);
                o[2 * p]     = fmaxf(v.x + bb[2 * p], 0.f);
                o[2 * p + 1] = fmaxf(v.y + bb[2 * p + 1], 0.f);
            }
            float4* dst = (float4*)(C + (size_t)r * 512 + c0);
            dst[0] = make_float4(o[0], o[1], o[2], o[3]);
            dst[1] = make_float4(o[4], o[5], o[6], o[7]);
        }
    } else {
        #pragma unroll
        for (int i = 0; i < 8; i++) {
            int r = br * 128 + tr * 8 + i;
            if (r >= n) break;
            float2 v0 = up2(acc[i][0]), v1 = up2(acc[i][1]);
            float2 v2 = up2(acc[i][2]), v3 = up2(acc[i][3]);
            float4* dst = (float4*)(C + (size_t)r * ncol + c0);
            dst[0] = make_float4(v0.x, v0.y, v1.x, v1.y);
            dst[1] = make_float4(v2.x, v2.y, v3.x, v3.y);
        }
    }
}

// ---------------- launch ----------------
extern "C" void kernel_launch(void* const* d_in, const int* in_sizes, int n_in,
                              void* d_out, int out_size) {
    const float* x  = (const float*)d_in[0];
    const void*  ei = d_in[1];                 // int32 or int64, probed on device
    const float* W1 = (const float*)d_in[2];
    const float* b1 = (const float*)d_in[3];
    const float* W2 = (const float*)d_in[4];
    const float* b2 = (const float*)d_in[5];
    int n = in_sizes[0] / DIN;
    int E = in_sizes[1] / 2;
    float* out = (float*)d_out;

    // output layout: concat(embedding [n,512], out [n,256]); fall back gracefully
    int full = (out_size >= n * (DHID + DOUT)) ? 1 : 0;
    float* out2 = out + ((size_t)out_size - (size_t)n * DOUT);
    float* embp = full ? out : g_emb;

    const int TB = 256;
    k_detect<<<1, TB>>>((const unsigned*)ei, E);
    k_init <<<(n + TB - 1) / TB, TB>>>(n);
    k_count<<<(E + TB - 1) / TB, TB>>>(ei, E, n);
    k_dinv <<<(n + TB - 1) / TB, TB>>>(n);
    k_scan <<<1, 1024>>>(n);
    k_fill <<<(E + TB - 1) / TB, TB>>>(ei, E, n);

    // layer 1: P1 = A_hat x ; h = relu(P1 @ W1^T + b1)
    k_prop<DIN, 1><<<((long)n * 32 + TB - 1) / TB, TB>>>(x, nullptr, nullptr, n);
    k_gemm<1><<<dim3((n + 127) / 128, DHID / 128), TB>>>(nullptr, W1, b1, out, full, n);

    // dropout (partitionable threefry): compact nonzeros of h, hash + scale in place
    int total = n * DHID;
    k_compact  <<<(total + TB - 1) / TB, TB>>>(embp, total);
    k_maskapply<<<2048, TB>>>(embp);

    // layer 2: T = emb @ W2^T ; out = A_hat T + b2   (propagate/linear commute)
    k_gemm<0><<<dim3((n + 127) / 128, DOUT / 128), TB>>>(out, W2, nullptr, nullptr, full, n);
    k_prop<DOUT, 0><<<((long)n * 32 + TB - 1) / TB, TB>>>(nullptr, out2, b2, n);
}

// round 11
// speedup vs baseline: 1.0980x; 1.0980x over previous
#include <cuda_runtime.h>
#include <cstdint>

#define NNODES 50000
#define EEDGES 800000
#define DIN 512
#define DHID 512
#define DOUT 256

// ---------------- static device scratch (no allocations allowed) ----------------
__device__ float    g_P1[(size_t)NNODES * DIN];    // propagate(x)
__device__ float    g_T [(size_t)NNODES * DOUT];   // emb @ W2^T
__device__ float    g_emb[(size_t)NNODES * DHID];  // embedding scratch (if out buffer lacks space)
__device__ int      g_deg[NNODES];
__device__ int      g_cursor[NNODES];
__device__ int      g_rowptr[NNODES + 1];
__device__ int      g_colidx[EEDGES];
__device__ float    g_dinv[NNODES];
__device__ int      g_is64;

// ---------------- packed f32x2 helpers ----------------
__device__ __forceinline__ unsigned long long pk2(float a, float b) {
    unsigned long long r;
    asm("mov.b64 %0, {%1, %2};" : "=l"(r) : "f"(a), "f"(b));
    return r;
}
__device__ __forceinline__ void fma2(unsigned long long& c, unsigned long long a, unsigned long long b) {
    asm("fma.rn.f32x2 %0, %1, %2, %0;" : "+l"(c) : "l"(a), "l"(b));
}
__device__ __forceinline__ float2 up2(unsigned long long v) {
    float2 f;
    asm("mov.b64 {%0, %1}, %2;" : "=f"(f.x), "=f"(f.y) : "l"(v));
    return f;
}

// ---------------- edge_index dtype probe + safe accessor ----------------
__global__ void k_detect(const unsigned* __restrict__ ei32, int E) {
    int any = 0;
    for (int i = threadIdx.x; i < 1024; i += blockDim.x)
        if (ei32[2 * i + 1] != 0u) any = 1;
    int found = __syncthreads_or(any);
    if (threadIdx.x == 0) g_is64 = found ? 0 : 1;
}

__device__ __forceinline__ int load_idx(const void* ei, int E, int which, int i, int n) {
    long long v;
    if (g_is64) v = ((const long long*)ei)[(size_t)which * E + i];
    else        v = (long long)((const int*)ei)[(size_t)which * E + i];
    if (v < 0) v = 0;
    if (v > n - 1) v = n - 1;
    return (int)v;
}

// ---------------- graph setup kernels ----------------
__global__ void k_init(int n) {
    int i = blockIdx.x * blockDim.x + threadIdx.x;
    if (i < n) { g_deg[i] = 0; g_cursor[i] = 0; }
}

__global__ void k_count(const void* __restrict__ ei, int E, int n) {
    int i = blockIdx.x * blockDim.x + threadIdx.x;
    if (i < E) {
        int d = load_idx(ei, E, 1, i, n);
        atomicAdd(&g_deg[d], 1);
    }
}

__global__ void k_dinv(int n) {
    int i = blockIdx.x * blockDim.x + threadIdx.x;
    if (i < n) g_dinv[i] = rsqrtf((float)(g_deg[i] + 1));
}

// exclusive scan of g_deg -> g_rowptr, single block of 1024 with shuffle scans
__global__ void k_scan(int n) {
    __shared__ int warpsum[32];
    __shared__ int s_carry;
    int tid = threadIdx.x, lane = tid & 31, wid = tid >> 5;
    if (tid == 0) s_carry = 0;
    __syncthreads();
    for (int base = 0; base < n; base += 1024) {
        int i = base + tid;
        int v = (i < n) ? g_deg[i] : 0;
        int incl = v;
        #pragma unroll
        for (int off = 1; off < 32; off <<= 1) {
            int t = __shfl_up_sync(0xffffffffu, incl, off);
            if (lane >= off) incl += t;
        }
        if (lane == 31) warpsum[wid] = incl;
        __syncthreads();
        if (wid == 0) {
            int w = warpsum[lane];
            int ws = w;
            #pragma unroll
            for (int off = 1; off < 32; off <<= 1) {
                int t = __shfl_up_sync(0xffffffffu, ws, off);
                if (lane >= off) ws += t;
            }
            warpsum[lane] = ws - w;  // exclusive warp offsets
        }
        __syncthreads();
        int excl = s_carry + warpsum[wid] + incl - v;
        if (i < n) g_rowptr[i] = excl;
        __syncthreads();
        if (tid == 1023) s_carry += warpsum[31] + incl;
        __syncthreads();
    }
    if (threadIdx.x == 0) g_rowptr[n] = s_carry;
}

__global__ void k_fill(const void* __restrict__ ei, int E, int n) {
    int i = blockIdx.x * blockDim.x + threadIdx.x;
    if (i < E) {
        int s = load_idx(ei, E, 0, i, n);
        int d = load_idx(ei, E, 1, i, n);
        int pos = atomicAdd(&g_cursor[d], 1);
        int slot = g_rowptr[d] + pos;
        if (slot < E) g_colidx[slot] = s;
    }
}

// ---------------- threefry2x32 (partitionable scheme), key = (0, 42) ----------------
// For flat element f: counter = (0, f); bits = o0 ^ o1; keep <=> bit31 == 0.
__device__ __forceinline__ void threefry2x32(unsigned x0, unsigned x1, unsigned& o0, unsigned& o1) {
    const unsigned k0 = 0u, k1 = 42u, k2 = 0x1BD11BDAu ^ k0 ^ k1;
    x0 += k0; x1 += k1;
#define TFR(r) { x0 += x1; x1 = (x1 << (r)) | (x1 >> (32 - (r))); x1 ^= x0; }
    TFR(13) TFR(15) TFR(26) TFR(6)   x0 += k1; x1 += k2 + 1u;
    TFR(17) TFR(29) TFR(16) TFR(24)  x0 += k2; x1 += k0 + 2u;
    TFR(13) TFR(15) TFR(26) TFR(6)   x0 += k0; x1 += k1 + 3u;
    TFR(17) TFR(29) TFR(16) TFR(24)  x0 += k1; x1 += k2 + 4u;
    TFR(13) TFR(15) TFR(26) TFR(6)   x0 += k2; x1 += k0 + 5u;
#undef TFR
    o0 = x0; o1 = x1;
}

__device__ __forceinline__ float drop_one(unsigned f, float h) {
    unsigned o0, o1;
    threefry2x32(0u, f, o0, o1);
    return ((o0 ^ o1) & 0x80000000u) ? 0.f : 2.f * h;
}

// ---------------- propagate: warp-per-node, CSR gather, no feature atomics ----------------
template <int D>
__global__ void k_prop(const float* __restrict__ X, float* __restrict__ Y,
                       const float* __restrict__ bias, int n) {
    int gw = (blockIdx.x * blockDim.x + threadIdx.x) >> 5;
    int lane = threadIdx.x & 31;
    if (gw >= n) return;
    const int G = D / 128;

    float di = g_dinv[gw];
    const float4* xs = (const float4*)(X + (size_t)gw * D);
    float4 acc[G];
    float ws = di * di;  // self loop
    #pragma unroll
    for (int g = 0; g < G; g++) {
        float4 v = xs[lane + 32 * g];
        acc[g] = make_float4(ws * v.x, ws * v.y, ws * v.z, ws * v.w);
    }
    int e0 = g_rowptr[gw], e1 = g_rowptr[gw + 1];
    int e = e0;
    for (; e + 1 < e1; e += 2) {
        int j0 = g_colidx[e], j1 = g_colidx[e + 1];
        float w0 = di * g_dinv[j0], w1 = di * g_dinv[j1];
        const float4* x0 = (const float4*)(X + (size_t)j0 * D);
        const float4* x1 = (const float4*)(X + (size_t)j1 * D);
        #pragma unroll
        for (int g = 0; g < G; g++) {
            float4 v0 = x0[lane + 32 * g];
            float4 v1 = x1[lane + 32 * g];
            acc[g].x = fmaf(w0, v0.x, fmaf(w1, v1.x, acc[g].x));
            acc[g].y = fmaf(w0, v0.y, fmaf(w1, v1.y, acc[g].y));
            acc[g].z = fmaf(w0, v0.z, fmaf(w1, v1.z, acc[g].z));
            acc[g].w = fmaf(w0, v0.w, fmaf(w1, v1.w, acc[g].w));
        }
    }
    if (e < e1) {
        int j0 = g_colidx[e];
        float w0 = di * g_dinv[j0];
        const float4* x0 = (const float4*)(X + (size_t)j0 * D);
        #pragma unroll
        for (int g = 0; g < G; g++) {
            float4 v0 = x0[lane + 32 * g];
            acc[g].x = fmaf(w0, v0.x, acc[g].x);
            acc[g].y = fmaf(w0, v0.y, acc[g].y);
            acc[g].z = fmaf(w0, v0.z, acc[g].z);
            acc[g].w = fmaf(w0, v0.w, acc[g].w);
        }
    }
    if (bias) {
        const float4* bb = (const float4*)bias;
        #pragma unroll
        for (int g = 0; g < G; g++) {
            float4 b = bb[lane + 32 * g];
            acc[g].x += b.x; acc[g].y += b.y; acc[g].z += b.z; acc[g].w += b.w;
        }
    }
    float4* ys = (float4*)(Y + (size_t)gw * D);
    #pragma unroll
    for (int g = 0; g < G; g++) ys[lane + 32 * g] = acc[g];
}

// ---------------- GEMM: C = A @ W^T, 128x128x16 tiles, packed fma.rn.f32x2 ----------------
// EPI==1: bias + relu + fused dropout epilogue (C stride 512).
// EPI==0: plain store (C stride gridDim.y*128).
#define STORE_TILE(buf)                                                        \
    {                                                                          \
        int kb = lkq * 4;                                                      \
        As[buf][(kb + 0) * S + lrow]      = ra0.x;                             \
        As[buf][(kb + 1) * S + lrow]      = ra0.y;                             \
        As[buf][(kb + 2) * S + lrow]      = ra0.z;                             \
        As[buf][(kb + 3) * S + lrow]      = ra0.w;                             \
        As[buf][(kb + 0) * S + lrow + 64] = ra1.x;                             \
        As[buf][(kb + 1) * S + lrow + 64] = ra1.y;                             \
        As[buf][(kb + 2) * S + lrow + 64] = ra1.z;                             \
        As[buf][(kb + 3) * S + lrow + 64] = ra1.w;                             \
        Bs[buf][(kb + 0) * S + lrow]      = rw0.x;                             \
        Bs[buf][(kb + 1) * S + lrow]      = rw0.y;                             \
        Bs[buf][(kb + 2) * S + lrow]      = rw0.z;                             \
        Bs[buf][(kb + 3) * S + lrow]      = rw0.w;                             \
        Bs[buf][(kb + 0) * S + lrow + 64] = rw1.x;                             \
        Bs[buf][(kb + 1) * S + lrow + 64] = rw1.y;                             \
        Bs[buf][(kb + 2) * S + lrow + 64] = rw1.z;                             \
        Bs[buf][(kb + 3) * S + lrow + 64] = rw1.w;                             \
    }

template <int EPI>
__global__ __launch_bounds__(256, 2) void k_gemm(const float* __restrict__ A,
                                                 const float* __restrict__ Wm,
                                                 const float* __restrict__ bias,
                                                 float* __restrict__ C,
                                                 int nrows) {
    const int S = 132;  // padded smem row stride (floats)
    __shared__ float As[2][16 * S];
    __shared__ float Bs[2][16 * S];

    int tid = threadIdx.x;
    int br = blockIdx.x, bc = blockIdx.y;
    int ncol = gridDim.y << 7;

    int lrow = tid >> 2;
    int lkq  = tid & 3;
    long ar0 = (long)br * 128 + lrow;       if (ar0 > nrows - 1) ar0 = nrows - 1;
    long ar1 = (long)br * 128 + lrow + 64;  if (ar1 > nrows - 1) ar1 = nrows - 1;
    long wr0 = (long)bc * 128 + lrow;
    long wr1 = wr0 + 64;
    const float* pa0 = A  + ar0 * 512 + lkq * 4;
    const float* pa1 = A  + ar1 * 512 + lkq * 4;
    const float* pw0 = Wm + wr0 * 512 + lkq * 4;
    const float* pw1 = Wm + wr1 * 512 + lkq * 4;

    float4 ra0 = *(const float4*)pa0;
    float4 ra1 = *(const float4*)pa1;
    float4 rw0 = *(const float4*)pw0;
    float4 rw1 = *(const float4*)pw1;
    STORE_TILE(0);
    __syncthreads();

    unsigned long long acc[8][4];
    #pragma unroll
    for (int i = 0; i < 8; i++)
        #pragma unroll
        for (int p = 0; p < 4; p++) acc[i][p] = 0ull;

    int tr = tid >> 4, tc = tid & 15;

    #pragma unroll 1
    for (int kt = 0; kt < 32; ++kt) {
        int cur = kt & 1;
        if (kt < 31) {  // prefetch next k-tile into registers
            ra0 = *(const float4*)(pa0 + (kt + 1) * 16);
            ra1 = *(const float4*)(pa1 + (kt + 1) * 16);
            rw0 = *(const float4*)(pw0 + (kt + 1) * 16);
            rw1 = *(const float4*)(pw1 + (kt + 1) * 16);
        }
        #pragma unroll
        for (int k = 0; k < 16; k++) {
            const float* as = &As[cur][k * S + tr * 8];
            float4 a0 = *(const float4*)as;
            float4 a1 = *(const float4*)(as + 4);
            const float* bs = &Bs[cur][k * S + tc * 8];
            float4 b0  = *(const float4*)bs;
            float4 b1v = *(const float4*)(bs + 4);
            unsigned long long bp0 = pk2(b0.x, b0.y),   bp1 = pk2(b0.z, b0.w);
            unsigned long long bp2 = pk2(b1v.x, b1v.y), bp3 = pk2(b1v.z, b1v.w);
            float av[8] = {a0.x, a0.y, a0.z, a0.w, a1.x, a1.y, a1.z, a1.w};
            #pragma unroll
            for (int i = 0; i < 8; i++) {
                unsigned long long ap = pk2(av[i], av[i]);
                fma2(acc[i][0], ap, bp0);
                fma2(acc[i][1], ap, bp1);
                fma2(acc[i][2], ap, bp2);
                fma2(acc[i][3], ap, bp3);
            }
        }
        if (kt < 31) { int nxt = cur ^ 1; STORE_TILE(nxt); }
        __syncthreads();
    }

    int c0 = bc * 128 + tc * 8;
    if (EPI == 1) {
        float4 bv0 = *(const float4*)(bias + c0);
        float4 bv1 = *(const float4*)(bias + c0 + 4);
        float bb[8] = {bv0.x, bv0.y, bv0.z, bv0.w, bv1.x, bv1.y, bv1.z, bv1.w};
        #pragma unroll
        for (int i = 0; i < 8; i++) {
            int r = br * 128 + tr * 8 + i;
            if (r >= nrows) break;
            unsigned fbase = (unsigned)r * 512u + (unsigned)c0;
            float o[8];
            #pragma unroll
            for (int p = 0; p < 4; p++) {
                float2 v = up2(acc[i][p]);
                float h0 = fmaxf(v.x + bb[2 * p], 0.f);
                float h1 = fmaxf(v.y + bb[2 * p + 1], 0.f);
                o[2 * p]     = drop_one(fbase + 2 * p,     h0);
                o[2 * p + 1] = drop_one(fbase + 2 * p + 1, h1);
            }
            float4* dst = (float4*)(C + (size_t)r * 512 + c0);
            dst[0] = make_float4(o[0], o[1], o[2], o[3]);
            dst[1] = make_float4(o[4], o[5], o[6], o[7]);
        }
    } else {
        #pragma unroll
        for (int i = 0; i < 8; i++) {
            int r = br * 128 + tr * 8 + i;
            if (r >= nrows) break;
            float2 v0 = up2(acc[i][0]), v1 = up2(acc[i][1]);
            float2 v2 = up2(acc[i][2]), v3 = up2(acc[i][3]);
            float4* dst = (float4*)(C + (size_t)r * ncol + c0);
            dst[0] = make_float4(v0.x, v0.y, v1.x, v1.y);
            dst[1] = make_float4(v2.x, v2.y, v3.x, v3.y);
        }
    }
}

// ---------------- launch ----------------
extern "C" void kernel_launch(void* const* d_in, const int* in_sizes, int n_in,
                              void* d_out, int out_size) {
    const float* x  = (const float*)d_in[0];
    const void*  ei = d_in[1];                 // int32 or int64, probed on device
    const float* W1 = (const float*)d_in[2];
    const float* b1 = (const float*)d_in[3];
    const float* W2 = (const float*)d_in[4];
    const float* b2 = (const float*)d_in[5];
    int n = in_sizes[0] / DIN;
    int E = in_sizes[1] / 2;
    float* out = (float*)d_out;

    // device scratch addresses (pure queries; capture-safe)
    float *p1, *tt, *embg;
    { void* p; cudaGetSymbolAddress(&p, g_P1);  p1   = (float*)p;
      cudaGetSymbolAddress(&p, g_T);            tt   = (float*)p;
      cudaGetSymbolAddress(&p, g_emb);          embg = (float*)p; }

    // output layout: concat(embedding [n,512], out [n,256]); fall back gracefully
    int full = (out_size >= n * (DHID + DOUT)) ? 1 : 0;
    float* out2 = out + ((size_t)out_size - (size_t)n * DOUT);
    float* embp = full ? out : embg;

    const int TB = 256;
    // ---- setup ----
    k_detect<<<1, TB>>>((const unsigned*)ei, E);
    k_init <<<(n + TB - 1) / TB, TB>>>(n);
    k_count<<<(E + TB - 1) / TB, TB>>>(ei, E, n);
    k_dinv <<<(n + TB - 1) / TB, TB>>>(n);
    k_scan <<<1, 1024>>>(n);
    k_fill <<<(E + TB - 1) / TB, TB>>>(ei, E, n);

    int blocks = (n + 127) / 128;

    // layer 1: P1 = A_hat x ; emb = dropout(relu(P1 @ W1^T + b1))  (dropout fused in epilogue)
    k_prop<DIN><<<((long)n * 32 + TB - 1) / TB, TB>>>(x, p1, nullptr, n);
    k_gemm<1><<<dim3(blocks, DHID / 128), TB>>>(p1, W1, b1, embp, n);

    // layer 2: T = emb @ W2^T ; out = A_hat T + b2   (propagate/linear commute)
    k_gemm<0><<<dim3(blocks, DOUT / 128), TB>>>(embp, W2, nullptr, tt, n);
    k_prop<DOUT><<<((long)n * 32 + TB - 1) / TB, TB>>>(tt, out2, b2, n);
}

// round 14
// speedup vs baseline: 1.7569x; 1.6001x over previous
#include <cuda_runtime.h>
#include <cuda_bf16.h>
#include <cstdint>

#define NNODES 50000
#define EEDGES 800000
#define DIN 512
#define DHID 512
#define DOUT 256

// ---------------- static device scratch (no allocations allowed) ----------------
__device__ __nv_bfloat16 g_Ahi[(size_t)NNODES * DIN];   // P1 hi
__device__ __nv_bfloat16 g_Alo[(size_t)NNODES * DIN];   // P1 lo
__device__ __nv_bfloat16 g_Ehi[(size_t)NNODES * DHID];  // emb hi
__device__ __nv_bfloat16 g_Elo[(size_t)NNODES * DHID];  // emb lo
__device__ __nv_bfloat16 g_W1hi[DHID * DIN];
__device__ __nv_bfloat16 g_W1lo[DHID * DIN];
__device__ __nv_bfloat16 g_W2hi[DOUT * DHID];
__device__ __nv_bfloat16 g_W2lo[DOUT * DHID];
__device__ float    g_T  [(size_t)NNODES * DOUT];   // emb @ W2^T
__device__ float    g_emb[(size_t)NNODES * DHID];   // embedding fallback buffer
__device__ int      g_deg[NNODES];
__device__ int      g_cursor[NNODES];
__device__ int      g_rowptr[NNODES + 1];
__device__ int      g_colidx[EEDGES];
__device__ float    g_dinv[NNODES];
__device__ int      g_is64;

// ---------------- warp-mma helpers (plain compute_103-legal PTX) ----------------
__device__ __forceinline__ uint32_t smem_u32(const void* p) {
    uint32_t a;
    asm("{ .reg .u64 t; cvta.to.shared.u64 t, %1; cvt.u32.u64 %0, t; }" : "=r"(a) : "l"(p));
    return a;
}
#define LDX4(r0, r1, r2, r3, addr)                                            \
    asm volatile("ldmatrix.sync.aligned.m8n8.x4.shared.b16 {%0,%1,%2,%3}, [%4];" \
                 : "=r"(r0), "=r"(r1), "=r"(r2), "=r"(r3) : "r"(addr))

__device__ __forceinline__ void mma16816(float* d, const uint32_t* a, const uint32_t* b) {
    asm volatile(
        "mma.sync.aligned.m16n8k16.row.col.f32.bf16.bf16.f32 "
        "{%0,%1,%2,%3}, {%4,%5,%6,%7}, {%8,%9}, {%0,%1,%2,%3};"
        : "+f"(d[0]), "+f"(d[1]), "+f"(d[2]), "+f"(d[3])
        : "r"(a[0]), "r"(a[1]), "r"(a[2]), "r"(a[3]), "r"(b[0]), "r"(b[1]));
}

// ---------------- edge_index dtype probe + safe accessor ----------------
__device__ __forceinline__ int load_idx(const void* ei, int E, int which, int i, int n) {
    long long v;
    if (g_is64) v = ((const long long*)ei)[(size_t)which * E + i];
    else        v = (long long)((const int*)ei)[(size_t)which * E + i];
    if (v < 0) v = 0;
    if (v > n - 1) v = n - 1;
    return (int)v;
}

// ---------------- setup kernels (merged so gemm1 is launch index 5) ----------------
__global__ void k_initdet(const unsigned* __restrict__ ei32, int E, int n) {
    int i = blockIdx.x * blockDim.x + threadIdx.x;
    if (i < n) { g_deg[i] = 0; g_cursor[i] = 0; }
    if (blockIdx.x == 0) {
        int any = 0;
        for (int t = threadIdx.x; t < 1024; t += blockDim.x)
            if (2 * t + 1 < 2 * E && ei32[2 * t + 1] != 0u) any = 1;
        int f = __syncthreads_or(any);
        if (threadIdx.x == 0) g_is64 = f ? 0 : 1;
    }
}

// blocks [0, EB): edge degree count. blocks [EB, EB+WB): convert W1/W2 fp32 -> bf16 hi/lo.
__global__ void k_countcvt(const void* __restrict__ ei, int E, int n, int EB,
                           const float* __restrict__ W1, const float* __restrict__ W2) {
    if ((int)blockIdx.x < EB) {
        int i = blockIdx.x * blockDim.x + threadIdx.x;
        if (i < E) {
            int d = load_idx(ei, E, 1, i, n);
            atomicAdd(&g_deg[d], 1);
        }
    } else {
        int j = (blockIdx.x - EB) * blockDim.x + threadIdx.x;
        const int W1N = DHID * DIN;
        if (j < W1N) {
            float v = W1[j];
            __nv_bfloat16 h = __float2bfloat16(v);
            g_W1hi[j] = h;
            g_W1lo[j] = __float2bfloat16(v - __bfloat162float(h));
        } else if (j < W1N + DOUT * DHID) {
            int q = j - W1N;
            float v = W2[q];
            __nv_bfloat16 h = __float2bfloat16(v);
            g_W2hi[q] = h;
            g_W2lo[q] = __float2bfloat16(v - __bfloat162float(h));
        }
    }
}

// exclusive scan of g_deg -> g_rowptr (+ fused dinv), single block of 1024
__global__ void k_scandinv(int n) {
    __shared__ int warpsum[32];
    __shared__ int s_carry;
    int tid = threadIdx.x, lane = tid & 31, wid = tid >> 5;
    if (tid == 0) s_carry = 0;
    __syncthreads();
    for (int base = 0; base < n; base += 1024) {
        int i = base + tid;
        int v = (i < n) ? g_deg[i] : 0;
        if (i < n) g_dinv[i] = rsqrtf((float)(v + 1));
        int incl = v;
        #pragma unroll
        for (int off = 1; off < 32; off <<= 1) {
            int t = __shfl_up_sync(0xffffffffu, incl, off);
            if (lane >= off) incl += t;
        }
        if (lane == 31) warpsum[wid] = incl;
        __syncthreads();
        if (wid == 0) {
            int w = warpsum[lane];
            int ws = w;
            #pragma unroll
            for (int off = 1; off < 32; off <<= 1) {
                int t = __shfl_up_sync(0xffffffffu, ws, off);
                if (lane >= off) ws += t;
            }
            warpsum[lane] = ws - w;
        }
        __syncthreads();
        int excl = s_carry + warpsum[wid] + incl - v;
        if (i < n) g_rowptr[i] = excl;
        __syncthreads();
        if (tid == 1023) s_carry += warpsum[31] + incl;
        __syncthreads();
    }
    if (threadIdx.x == 0) g_rowptr[n] = s_carry;
}

__global__ void k_fill(const void* __restrict__ ei, int E, int n) {
    int i = blockIdx.x * blockDim.x + threadIdx.x;
    if (i < E) {
        int s = load_idx(ei, E, 0, i, n);
        int d = load_idx(ei, E, 1, i, n);
        int pos = atomicAdd(&g_cursor[d], 1);
        int slot = g_rowptr[d] + pos;
        if (slot < E) g_colidx[slot] = s;
    }
}

// ---------------- threefry2x32 (partitionable), key = (0, 42); keep <=> bit31(o0^o1)==0 ----
__device__ __forceinline__ float drop_one(unsigned f, float h) {
    const unsigned k0 = 0u, k1 = 42u, k2 = 0x1BD11BDAu ^ k0 ^ k1;
    unsigned x0 = 0u + k0, x1 = f + k1;
#define TFR(r) { x0 += x1; x1 = __funnelshift_l(x1, x1, r); x1 ^= x0; }
    TFR(13) TFR(15) TFR(26) TFR(6)   x0 += k1; x1 += k2 + 1u;
    TFR(17) TFR(29) TFR(16) TFR(24)  x0 += k2; x1 += k0 + 2u;
    TFR(13) TFR(15) TFR(26) TFR(6)   x0 += k0; x1 += k1 + 3u;
    TFR(17) TFR(29) TFR(16) TFR(24)  x0 += k1; x1 += k2 + 4u;
    TFR(13) TFR(15) TFR(26) TFR(6)   x0 += k2; x1 += k0 + 5u;
#undef TFR
    return ((x0 ^ x1) & 0x80000000u) ? 0.f : 2.f * h;
}

__device__ __forceinline__ unsigned pkbf(float a, float b) {
    __nv_bfloat162 t = __floats2bfloat162_rn(a, b);
    return *(unsigned*)&t;
}

// ---------------- propagate: warp-per-node, CSR gather ----------------
// OUTB==1: write bf16 hi/lo (Yhi/Ylo). OUTB==0: write fp32 Y (+bias).
template <int D, int OUTB>
__global__ void k_prop(const float* __restrict__ X, float* __restrict__ Y,
                       __nv_bfloat16* __restrict__ Yhi, __nv_bfloat16* __restrict__ Ylo,
                       const float* __restrict__ bias, int n) {
    int gw = (blockIdx.x * blockDim.x + threadIdx.x) >> 5;
    int lane = threadIdx.x & 31;
    if (gw >= n) return;
    const int G = D / 128;

    float di = g_dinv[gw];
    const float4* xs = (const float4*)(X + (size_t)gw * D);
    float4 acc[G];
    float ws = di * di;  // self loop
    #pragma unroll
    for (int g = 0; g < G; g++) {
        float4 v = xs[lane + 32 * g];
        acc[g] = make_float4(ws * v.x, ws * v.y, ws * v.z, ws * v.w);
    }
    int e0 = g_rowptr[gw], e1 = g_rowptr[gw + 1];
    int e = e0;
    for (; e + 1 < e1; e += 2) {
        int j0 = g_colidx[e], j1 = g_colidx[e + 1];
        float w0 = di * g_dinv[j0], w1 = di * g_dinv[j1];
        const float4* x0 = (const float4*)(X + (size_t)j0 * D);
        const float4* x1 = (const float4*)(X + (size_t)j1 * D);
        #pragma unroll
        for (int g = 0; g < G; g++) {
            float4 v0 = x0[lane + 32 * g];
            float4 v1 = x1[lane + 32 * g];
            acc[g].x = fmaf(w0, v0.x, fmaf(w1, v1.x, acc[g].x));
            acc[g].y = fmaf(w0, v0.y, fmaf(w1, v1.y, acc[g].y));
            acc[g].z = fmaf(w0, v0.z, fmaf(w1, v1.z, acc[g].z));
            acc[g].w = fmaf(w0, v0.w, fmaf(w1, v1.w, acc[g].w));
        }
    }
    if (e < e1) {
        int j0 = g_colidx[e];
        float w0 = di * g_dinv[j0];
        const float4* x0 = (const float4*)(X + (size_t)j0 * D);
        #pragma unroll
        for (int g = 0; g < G; g++) {
            float4 v0 = x0[lane + 32 * g];
            acc[g].x = fmaf(w0, v0.x, acc[g].x);
            acc[g].y = fmaf(w0, v0.y, acc[g].y);
            acc[g].z = fmaf(w0, v0.z, acc[g].z);
            acc[g].w = fmaf(w0, v0.w, acc[g].w);
        }
    }
    if (OUTB == 1) {
        uint2* yh = (uint2*)(Yhi + (size_t)gw * D);
        uint2* yl = (uint2*)(Ylo + (size_t)gw * D);
        #pragma unroll
        for (int g = 0; g < G; g++) {
            float4 v = acc[g];
            __nv_bfloat16 hx = __float2bfloat16(v.x), hy = __float2bfloat16(v.y);
            __nv_bfloat16 hz = __float2bfloat16(v.z), hw = __float2bfloat16(v.w);
            unsigned hi01 = ((unsigned)__bfloat16_as_ushort(hy) << 16) | __bfloat16_as_ushort(hx);
            unsigned hi23 = ((unsigned)__bfloat16_as_ushort(hw) << 16) | __bfloat16_as_ushort(hz);
            yh[lane + 32 * g] = make_uint2(hi01, hi23);
            unsigned lo01 = pkbf(v.x - __bfloat162float(hx), v.y - __bfloat162float(hy));
            unsigned lo23 = pkbf(v.z - __bfloat162float(hz), v.w - __bfloat162float(hw));
            yl[lane + 32 * g] = make_uint2(lo01, lo23);
        }
    } else {
        if (bias) {
            const float4* bb = (const float4*)bias;
            #pragma unroll
            for (int g = 0; g < G; g++) {
                float4 b = bb[lane + 32 * g];
                acc[g].x += b.x; acc[g].y += b.y; acc[g].z += b.z; acc[g].w += b.w;
            }
        }
        float4* ys = (float4*)(Y + (size_t)gw * D);
        #pragma unroll
        for (int g = 0; g < G; g++) ys[lane + 32 * g] = acc[g];
    }
}

// ---------------- mma.sync GEMM: C = A @ W^T, bf16 hi/lo split (3 MMAs / product) --------
// CTA tile 128x128, 512 threads (16 warps, 32x32 warp tiles), K-chunks of 32, double buffer.
// smem per array tile: 128 rows x 32 bf16, row stride 40 bf16 (80B, conflict-free ldmatrix).
// EPI==1: bias+relu+dropout, write fp32 C (stride 512) + bf16 hi/lo (Ehi/Elo).
// EPI==0: plain fp32 C (stride ncol).
#define STR 40
#define TILE_B (128 * STR * 2)   // 10240 bytes per array tile
template <int EPI>
__global__ __launch_bounds__(512)
void k_gemm_mma(const __nv_bfloat16* __restrict__ Ahi, const __nv_bfloat16* __restrict__ Alo,
                const __nv_bfloat16* __restrict__ Whi, const __nv_bfloat16* __restrict__ Wlo,
                const float* __restrict__ bias, float* __restrict__ C,
                __nv_bfloat16* __restrict__ Ehi, __nv_bfloat16* __restrict__ Elo,
                int nrows, int ncol) {
    extern __shared__ char dsm[];   // 2 stages x 4 arrays x TILE_B = 81920 B
    int tid = threadIdx.x;
    int warp = tid >> 5, lane = tid & 31;
    int br = blockIdx.x, bc = blockIdx.y;
    int m0 = (warp >> 2) * 32;      // warp tile row base within CTA tile
    int n0 = (warp & 3) * 32;       // warp tile col base

    // loader mapping: one uint4 (8 bf16) per thread per array per stage
    int lr = tid >> 2;              // row 0..127
    int lc = tid & 3;               // k chunk (8 bf16)
    long arow = (long)br * 128 + lr; if (arow > nrows - 1) arow = nrows - 1;
    long wrow = (long)bc * 128 + lr;
    const __nv_bfloat16* srcp[4] = {Ahi + arow * 512 + lc * 8, Alo + arow * 512 + lc * 8,
                                    Whi + wrow * 512 + lc * 8, Wlo + wrow * 512 + lc * 8};
    int soff = (lr * STR + lc * 8) * 2;   // byte offset inside a tile

    uint32_t smbase = smem_u32(dsm);

    float acc[2][4][4];
    #pragma unroll
    for (int mt = 0; mt < 2; mt++)
        #pragma unroll
        for (int nt = 0; nt < 4; nt++)
            #pragma unroll
            for (int q = 0; q < 4; q++) acc[mt][nt][q] = 0.f;

    // ldmatrix element offsets (bf16 units) within a tile, per k16 kk:
    //   A (m16k16): row m0+mt*16+(lane&15), col kk + ((lane>>4)<<3)
    //   B (n16k16): row n0+ng*16+(lane&7)+((lane>>4)<<3), col kk + (((lane>>3)&1)<<3)
    int a_r = (lane & 15);
    int a_c = (lane >> 4) << 3;
    int b_r = (lane & 7) + ((lane >> 4) << 3);
    int b_c = ((lane >> 3) & 1) << 3;

    // prologue: stage 0
    {
        uint4 v[4];
        #pragma unroll
        for (int t = 0; t < 4; t++) v[t] = *(const uint4*)srcp[t];
        #pragma unroll
        for (int t = 0; t < 4; t++) *(uint4*)(dsm + t * TILE_B + soff) = v[t];
    }
    __syncthreads();

    #pragma unroll 1
    for (int s = 0; s < 16; s++) {
        uint4 v[4];
        if (s < 15) {
            #pragma unroll
            for (int t = 0; t < 4; t++) v[t] = *(const uint4*)(srcp[t] + (s + 1) * 32);
        }
        uint32_t stb = smbase + (uint32_t)((s & 1) * 4) * TILE_B;
        #pragma unroll
        for (int kk = 0; kk < 32; kk += 16) {
            uint32_t ah[2][4], al[2][4], bh[4][2], bl[4][2];
            #pragma unroll
            for (int mt = 0; mt < 2; mt++) {
                uint32_t ao = stb + (uint32_t)(((m0 + mt * 16 + a_r) * STR + kk + a_c) * 2);
                LDX4(ah[mt][0], ah[mt][1], ah[mt][2], ah[mt][3], ao);
                LDX4(al[mt][0], al[mt][1], al[mt][2], al[mt][3], ao + TILE_B);
            }
            #pragma unroll
            for (int ng = 0; ng < 2; ng++) {
                uint32_t bo = stb + 2u * TILE_B
                            + (uint32_t)(((n0 + ng * 16 + b_r) * STR + kk + b_c) * 2);
                LDX4(bh[2 * ng][0], bh[2 * ng][1], bh[2 * ng + 1][0], bh[2 * ng + 1][1], bo);
                LDX4(bl[2 * ng][0], bl[2 * ng][1], bl[2 * ng + 1][0], bl[2 * ng + 1][1],
                     bo + TILE_B);
            }
            #pragma unroll
            for (int mt = 0; mt < 2; mt++)
                #pragma unroll
                for (int nt = 0; nt < 4; nt++) {
                    mma16816(acc[mt][nt], ah[mt], bh[nt]);
                    mma16816(acc[mt][nt], ah[mt], bl[nt]);
                    mma16816(acc[mt][nt], al[mt], bh[nt]);
                }
        }
        if (s < 15) {
            char* nb = dsm + ((s + 1) & 1) * 4 * TILE_B;
            #pragma unroll
            for (int t = 0; t < 4; t++) *(uint4*)(nb + t * TILE_B + soff) = v[t];
        }
        __syncthreads();
    }

    // epilogue. D frag: q0,q1 -> row (lane>>2), cols (lane&3)*2,+1 ; q2,q3 -> row +8.
    #pragma unroll
    for (int mt = 0; mt < 2; mt++) {
        #pragma unroll
        for (int nt = 0; nt < 4; nt++) {
            int r = br * 128 + m0 + mt * 16 + (lane >> 2);
            int c = bc * 128 + n0 + nt * 8 + (lane & 3) * 2;
            #pragma unroll
            for (int h = 0; h < 2; h++) {      // h=0: row r, h=1: row r+8
                int rr = r + h * 8;
                if (rr >= nrows) continue;
                float v0 = acc[mt][nt][2 * h], v1 = acc[mt][nt][2 * h + 1];
                if (EPI == 1) {
                    float h0 = fmaxf(v0 + bias[c], 0.f);
                    float h1 = fmaxf(v1 + bias[c + 1], 0.f);
                    unsigned f = (unsigned)rr * 512u + (unsigned)c;
                    float o0 = drop_one(f, h0);
                    float o1 = drop_one(f + 1, h1);
                    *(float2*)(C + (size_t)rr * 512 + c) = make_float2(o0, o1);
                    __nv_bfloat16 e0 = __float2bfloat16(o0), e1 = __float2bfloat16(o1);
                    unsigned hi = ((unsigned)__bfloat16_as_ushort(e1) << 16)
                                | __bfloat16_as_ushort(e0);
                    *(unsigned*)(Ehi + (size_t)rr * 512 + c) = hi;
                    *(unsigned*)(Elo + (size_t)rr * 512 + c) =
                        pkbf(o0 - __bfloat162float(e0), o1 - __bfloat162float(e1));
                } else {
                    *(float2*)(C + (size_t)rr * ncol + c) = make_float2(v0, v1);
                }
            }
        }
    }
}

// ---------------- launch ----------------
extern "C" void kernel_launch(void* const* d_in, const int* in_sizes, int n_in,
                              void* d_out, int out_size) {
    const float* x  = (const float*)d_in[0];
    const void*  ei = d_in[1];
    const float* W1 = (const float*)d_in[2];
    const float* b1 = (const float*)d_in[3];
    const float* W2 = (const float*)d_in[4];
    const float* b2 = (const float*)d_in[5];
    int n = in_sizes[0] / DIN;
    int E = in_sizes[1] / 2;
    float* out = (float*)d_out;

    // device scratch addresses (pure queries; capture-safe)
    __nv_bfloat16 *ahi, *alo, *ehi, *elo, *w1h, *w1l, *w2h, *w2l;
    float *tt, *embg;
    { void* p;
      cudaGetSymbolAddress(&p, g_Ahi);  ahi = (__nv_bfloat16*)p;
      cudaGetSymbolAddress(&p, g_Alo);  alo = (__nv_bfloat16*)p;
      cudaGetSymbolAddress(&p, g_Ehi);  ehi = (__nv_bfloat16*)p;
      cudaGetSymbolAddress(&p, g_Elo);  elo = (__nv_bfloat16*)p;
      cudaGetSymbolAddress(&p, g_W1hi); w1h = (__nv_bfloat16*)p;
      cudaGetSymbolAddress(&p, g_W1lo); w1l = (__nv_bfloat16*)p;
      cudaGetSymbolAddress(&p, g_W2hi); w2h = (__nv_bfloat16*)p;
      cudaGetSymbolAddress(&p, g_W2lo); w2l = (__nv_bfloat16*)p;
      cudaGetSymbolAddress(&p, g_T);    tt   = (float*)p;
      cudaGetSymbolAddress(&p, g_emb);  embg = (float*)p; }

    int full = (out_size >= n * (DHID + DOUT)) ? 1 : 0;
    float* out2 = out + ((size_t)out_size - (size_t)n * DOUT);
    float* embp = full ? out : embg;

    const int TB = 256;
    const int SMEM = 8 * TILE_B;   // 81920 B
    cudaFuncSetAttribute(k_gemm_mma<1>, cudaFuncAttributeMaxDynamicSharedMemorySize, SMEM);
    cudaFuncSetAttribute(k_gemm_mma<0>, cudaFuncAttributeMaxDynamicSharedMemorySize, SMEM);

    int EB = (E + TB - 1) / TB;
    int WB = (DHID * DIN + DOUT * DHID + TB - 1) / TB;
    int nb = (n + 127) / 128;

    // launches 0..4 (setup + prop1); gemm1 at index 5 for ncu -s 5 -c 1
    k_initdet <<<(n + TB - 1) / TB, TB>>>((const unsigned*)ei, E, n);
    k_countcvt<<<EB + WB, TB>>>(ei, E, n, EB, W1, W2);
    k_scandinv<<<1, 1024>>>(n);
    k_fill    <<<EB, TB>>>(ei, E, n);
    k_prop<DIN, 1><<<((long)n * 32 + TB - 1) / TB, TB>>>(x, nullptr, ahi, alo, nullptr, n);

    // layer 1: emb = dropout(relu(P1 @ W1^T + b1)); emb also emitted as bf16 hi/lo
    k_gemm_mma<1><<<dim3(nb, DHID / 128), 512, SMEM>>>(ahi, alo, w1h, w1l, b1,
                                                       embp, ehi, elo, n, DHID);
    // layer 2: T = emb @ W2^T ; out = A_hat T + b2   (propagate/linear commute)
    k_gemm_mma<0><<<dim3(nb, DOUT / 128), 512, SMEM>>>(ehi, elo, w2h, w2l, nullptr,
                                                       tt, nullptr, nullptr, n, DOUT);
    k_prop<DOUT, 0><<<((long)n * 32 + TB - 1) / TB, TB>>>(tt, out2, nullptr, nullptr, b2, n);
}